// round 16
// baseline (speedup 1.0000x reference)
#include <cuda_runtime.h>
#include <cstdint>

#define B 2
#define N 2048
#define C 768
#define CG 192                     // C/4 float4 groups
#define G1 256
#define G2 256
#define G3 256
#define T 256
#define SCOP 4                     // staged copies for s (64 contenders/addr)
#define VCOP 4                     // staged copies for v (64 contenders/addr)

// Epoch double-buffered staged accumulators (zero-init symbols).
__device__ float g_sa[2][SCOP][B][C];
__device__ float g_va[2][VCOP][B][C];
__device__ unsigned g_cnt[3];      // per-kernel monotonic launch counters

__device__ __forceinline__ float4 f4add(float4 a, float4 b) {
    return make_float4(a.x + b.x, a.y + b.y, a.z + b.z, a.w + b.w);
}

// ---- K1: column-sums of X -> staged atomics into s; prefetch W to L2;
//          zero next epoch's buffers. grid 256, block 256. ----
__global__ void __launch_bounds__(T) k1_colsum(const float4* __restrict__ X4,
                                               const float4* __restrict__ W4) {
    __shared__ int e_sh;
    const int ct = blockIdx.x, tid = threadIdx.x;
    if (tid == 0) {
        unsigned old = atomicAdd(&g_cnt[0], 1u);   // per-CTA old = k*G1 + j
        e_sh = (int)((old / G1) & 1u);             // same k for all CTAs
    }
    __syncthreads();
    const int e = e_sh;

    // Zero NEXT epoch's buffers: 6144 floats each / 256 CTAs = 24 each.
    {
        float* zs = (float*)g_sa[1 - e];
        float* zv = (float*)g_va[1 - e];
        if (tid < 24) zs[ct * 24 + tid] = 0.f;
        else if (tid < 48) zv[ct * 24 + (tid - 24)] = 0.f;
    }
    // Prefetch W into L2: 36864 lines of 128B / 256 CTAs = 144 lines.
    if (tid >= 48 && tid < 192) {
        const char* wb = (const char*)W4;
        asm volatile("prefetch.global.L2 [%0];"
                     :: "l"(wb + ((size_t)ct * 144 + (tid - 48)) * 128));
    }

    const int b = ct & 1, chunk = ct >> 1;         // 128 chunks of 16 rows
    if (tid < CG) {
        const float4* p = X4 + ((size_t)b * N + chunk * 16) * CG + tid;
        float4 a0 = make_float4(0.f, 0.f, 0.f, 0.f), a1 = a0;
#pragma unroll
        for (int r = 0; r < 16; r += 2) {
            a0 = f4add(a0, p[(size_t)r * CG]);
            a1 = f4add(a1, p[(size_t)(r + 1) * CG]);
        }
        float4 s = f4add(a0, a1);
        float* dst = &g_sa[e][ct & (SCOP - 1)][b][tid * 4];
        atomicAdd(dst + 0, s.x);
        atomicAdd(dst + 1, s.y);
        atomicAdd(dst + 2, s.z);
        atomicAdd(dst + 3, s.w);
    }
}

// ---- K2: u_j = Wk_j . s (3 rows/CTA); staged atomics of u_j*Wq_j into v.
//          grid 256, block 256. W is L2-hot from K1's prefetch. ----
__global__ void __launch_bounds__(T) k2_rank1(const float4* __restrict__ W4) {
    __shared__ float4 sh[2 * CG];
    __shared__ float u0s[3], u1s[3];
    __shared__ int e_sh;
    const int ct = blockIdx.x, tid = threadIdx.x;
    const int wid = tid >> 5, lane = tid & 31;
    if (tid == 0) {
        unsigned old = atomicAdd(&g_cnt[1], 1u);
        e_sh = (int)((old / G2) & 1u);
    }
    __syncthreads();
    const int e = e_sh;
    const int j0 = ct * 3;

    // Stage s (sum SCOP copies, both batches).
    for (int i = tid; i < 2 * CG; i += T) {
        int bb = (i < CG) ? 0 : 1;
        int idx = (i < CG) ? i : i - CG;
        float4 acc = make_float4(0.f, 0.f, 0.f, 0.f);
#pragma unroll
        for (int c = 0; c < SCOP; ++c)
            acc = f4add(acc, *(const float4*)&g_sa[e][c][bb][idx * 4]);
        sh[i] = acc;
    }
    __syncthreads();
    if (wid < 3) {
        const float4* row = W4 + (size_t)(C + j0 + wid) * CG;   // Wk (L2)
        float a0 = 0.f, a1 = 0.f;
#pragma unroll
        for (int k = 0; k < 6; ++k) {
            int c4 = lane + k * 32;
            float4 w  = row[c4];
            float4 v0 = sh[c4];
            float4 v1 = sh[CG + c4];
            a0 += w.x * v0.x + w.y * v0.y + w.z * v0.z + w.w * v0.w;
            a1 += w.x * v1.x + w.y * v1.y + w.z * v1.z + w.w * v1.w;
        }
#pragma unroll
        for (int o = 16; o > 0; o >>= 1) {
            a0 += __shfl_down_sync(0xFFFFFFFFu, a0, o);
            a1 += __shfl_down_sync(0xFFFFFFFFu, a1, o);
        }
        if (lane == 0) { u0s[wid] = a0; u1s[wid] = a1; }
    }
    __syncthreads();
    if (tid < CG) {
        float4 w0 = W4[(size_t)j0 * CG + tid];                  // Wq (L2)
        float4 w1 = W4[(size_t)(j0 + 1) * CG + tid];
        float4 w2 = W4[(size_t)(j0 + 2) * CG + tid];
        float4 a0 = make_float4(
            w0.x * u0s[0] + w1.x * u0s[1] + w2.x * u0s[2],
            w0.y * u0s[0] + w1.y * u0s[1] + w2.y * u0s[2],
            w0.z * u0s[0] + w1.z * u0s[1] + w2.z * u0s[2],
            w0.w * u0s[0] + w1.w * u0s[1] + w2.w * u0s[2]);
        float4 a1 = make_float4(
            w0.x * u1s[0] + w1.x * u1s[1] + w2.x * u1s[2],
            w0.y * u1s[0] + w1.y * u1s[1] + w2.y * u1s[2],
            w0.z * u1s[0] + w1.z * u1s[1] + w2.z * u1s[2],
            w0.w * u1s[0] + w1.w * u1s[1] + w2.w * u1s[2]);
        int vc = ct & (VCOP - 1);
        float* d0 = &g_va[e][vc][0][tid * 4];
        float* d1 = &g_va[e][vc][1][tid * 4];
        atomicAdd(d0 + 0, a0.x); atomicAdd(d0 + 1, a0.y);
        atomicAdd(d0 + 2, a0.z); atomicAdd(d0 + 3, a0.w);
        atomicAdd(d1 + 0, a1.x); atomicAdd(d1 + 1, a1.y);
        atomicAdd(d1 + 2, a1.z); atomicAdd(d1 + 3, a1.w);
    }
}

// ---- K3: scores[b,n] = 0.125 * X[b,n,:] . v[b]. X is L2-hot from K1.
//          grid 256 (16 rows/CTA), block 256. ----
__global__ void __launch_bounds__(T) k3_scores(const float4* __restrict__ X4,
                                               float* __restrict__ out) {
    __shared__ float4 sh[CG];
    __shared__ int e_sh;
    const int ct = blockIdx.x, tid = threadIdx.x;
    const int wid = tid >> 5, lane = tid & 31;
    if (tid == 0) {
        unsigned old = atomicAdd(&g_cnt[2], 1u);
        e_sh = (int)((old / G3) & 1u);
    }
    __syncthreads();
    const int e = e_sh;
    const int b = ct & 1, chunk = ct >> 1;

    if (tid < CG) {
        float4 acc = make_float4(0.f, 0.f, 0.f, 0.f);
#pragma unroll
        for (int c = 0; c < VCOP; ++c)
            acc = f4add(acc, *(const float4*)&g_va[e][c][b][tid * 4]);
        sh[tid] = acc;
    }
    __syncthreads();

    int nbase = chunk * 16 + wid * 2;
    float a[2];
#pragma unroll
    for (int r = 0; r < 2; ++r) {
        const float4* x = X4 + ((size_t)b * N + nbase + r) * CG;
        float acc = 0.f;
#pragma unroll
        for (int k = 0; k < 6; ++k) {
            int c4 = lane + k * 32;
            float4 xv = x[c4];
            float4 vv = sh[c4];
            acc += xv.x * vv.x + xv.y * vv.y + xv.z * vv.z + xv.w * vv.w;
        }
        a[r] = acc;
    }
#pragma unroll
    for (int o = 16; o > 0; o >>= 1) {
#pragma unroll
        for (int r = 0; r < 2; ++r)
            a[r] += __shfl_down_sync(0xFFFFFFFFu, a[r], o);
    }
    if (lane == 0) {
#pragma unroll
        for (int r = 0; r < 2; ++r)
            out[b * N + nbase + r] = 0.125f * a[r];
    }
}

extern "C" void kernel_launch(void* const* d_in, const int* in_sizes, int n_in,
                              void* d_out, int out_size) {
    const float4* X4 = (const float4*)d_in[0];  // [2, 2048, 768] f32
    const float4* W4 = (const float4*)d_in[1];  // [1536, 768] f32
    float* out = (float*)d_out;                 // [2, 2048] f32
    (void)in_sizes; (void)n_in; (void)out_size;

    k1_colsum<<<G1, T>>>(X4, W4);
    k2_rank1<<<G2, T>>>(W4);
    k3_scores<<<G3, T>>>(X4, out);
}

// round 17
// speedup vs baseline: 1.0646x; 1.0646x over previous
#include <cuda_runtime.h>
#include <cstdint>

#define B 2
#define N 2048
#define C 768
#define CG 192                     // C/4 float4 groups
#define G1 512
#define G2 128
#define G3 256
#define T1 192
#define T 256
#define SCOP 8                     // staged copies for s (32 contenders/addr)
#define VCOP 4                     // staged copies for v (32 contenders/addr)

// Epoch double-buffered staged accumulators (zero-init symbols).
__device__ float g_sa[2][SCOP][B][C];
__device__ float g_va[2][VCOP][B][C];
__device__ unsigned g_cnt[3];      // per-kernel monotonic launch counters

__device__ __forceinline__ float4 f4add(float4 a, float4 b) {
    return make_float4(a.x + b.x, a.y + b.y, a.z + b.z, a.w + b.w);
}

// ---- K1: column-sums of X -> staged atomics into s. 512 CTAs x 8 rows,
//          array-batched loads (MLP=8/thread). Also zeros next epoch's
//          buffers and prefetches W into L2. ----
__global__ void __launch_bounds__(T1) k1_colsum(const float4* __restrict__ X4,
                                                const float4* __restrict__ W4) {
    __shared__ int e_sh;
    const int ct = blockIdx.x, tid = threadIdx.x;
    if (tid == 0) {
        unsigned old = atomicAdd(&g_cnt[0], 1u);
        e_sh = (int)((old / G1) & 1u);
    }
    __syncthreads();
    const int e = e_sh;

    // Zero NEXT epoch: s = 8*2*768 = 12288 floats (24/CTA), v = 4*2*768 = 6144 (12/CTA).
    {
        float* zs = (float*)g_sa[1 - e];
        float* zv = (float*)g_va[1 - e];
        if (tid < 24) zs[ct * 24 + tid] = 0.f;
        else if (tid < 36) zv[ct * 12 + (tid - 24)] = 0.f;
    }
    // Prefetch W into L2: 36864 lines of 128B / 512 CTAs = 72/CTA.
    if (tid >= 64 && tid < 136) {
        const char* wb = (const char*)W4;
        asm volatile("prefetch.global.L2 [%0];"
                     :: "l"(wb + ((size_t)ct * 72 + (tid - 64)) * 128));
    }

    const int b = ct & 1, chunk = ct >> 1;         // 256 chunks of 8 rows
    const float4* p = X4 + ((size_t)b * N + chunk * 8) * CG + tid;
    float4 v[8];
#pragma unroll
    for (int r = 0; r < 8; ++r)
        v[r] = p[(size_t)r * CG];                  // 8 independent LDG.128
    float4 s = f4add(f4add(f4add(v[0], v[1]), f4add(v[2], v[3])),
                     f4add(f4add(v[4], v[5]), f4add(v[6], v[7])));
    // Copy index decoupled from batch bit: per (copy,b) address gets 32 CTAs.
    float* dst = &g_sa[e][(ct >> 1) & (SCOP - 1)][b][tid * 4];
    atomicAdd(dst + 0, s.x);
    atomicAdd(dst + 1, s.y);
    atomicAdd(dst + 2, s.z);
    atomicAdd(dst + 3, s.w);
}

// ---- K2: u_j = Wk_j . s (6 rows/CTA); staged atomics of u_j*Wq_j into v.
//          128 CTAs x 256 thr. W is L2-hot from K1's prefetch. ----
__global__ void __launch_bounds__(T) k2_rank1(const float4* __restrict__ W4) {
    __shared__ float4 sh[2 * CG];
    __shared__ float u0s[6], u1s[6];
    __shared__ int e_sh;
    const int ct = blockIdx.x, tid = threadIdx.x;
    const int wid = tid >> 5, lane = tid & 31;
    if (tid == 0) {
        unsigned old = atomicAdd(&g_cnt[1], 1u);
        e_sh = (int)((old / G2) & 1u);
    }
    __syncthreads();
    const int e = e_sh;
    const int j0 = ct * 6;

    // Stage s: sum SCOP copies, both batches (384 f4 slots).
    for (int i = tid; i < 2 * CG; i += T) {
        int bb = (i < CG) ? 0 : 1;
        int idx = (i < CG) ? i : i - CG;
        float4 acc = make_float4(0.f, 0.f, 0.f, 0.f);
#pragma unroll
        for (int c = 0; c < SCOP; ++c)
            acc = f4add(acc, *(const float4*)&g_sa[e][c][bb][idx * 4]);
        sh[i] = acc;
    }
    __syncthreads();
    if (wid < 6) {
        const float4* row = W4 + (size_t)(C + j0 + wid) * CG;   // Wk (L2)
        float a0 = 0.f, a1 = 0.f;
#pragma unroll
        for (int k = 0; k < 6; ++k) {
            int c4 = lane + k * 32;
            float4 w  = row[c4];
            float4 v0 = sh[c4];
            float4 v1 = sh[CG + c4];
            a0 += w.x * v0.x + w.y * v0.y + w.z * v0.z + w.w * v0.w;
            a1 += w.x * v1.x + w.y * v1.y + w.z * v1.z + w.w * v1.w;
        }
#pragma unroll
        for (int o = 16; o > 0; o >>= 1) {
            a0 += __shfl_down_sync(0xFFFFFFFFu, a0, o);
            a1 += __shfl_down_sync(0xFFFFFFFFu, a1, o);
        }
        if (lane == 0) { u0s[wid] = a0; u1s[wid] = a1; }
    }
    __syncthreads();
    if (tid < CG) {
        float4 a0 = make_float4(0.f, 0.f, 0.f, 0.f);
        float4 a1 = make_float4(0.f, 0.f, 0.f, 0.f);
#pragma unroll
        for (int jj = 0; jj < 6; ++jj) {
            float4 w = W4[(size_t)(j0 + jj) * CG + tid];        // Wq (L2)
            float u0 = u0s[jj], u1 = u1s[jj];
            a0 = make_float4(fmaf(w.x, u0, a0.x), fmaf(w.y, u0, a0.y),
                             fmaf(w.z, u0, a0.z), fmaf(w.w, u0, a0.w));
            a1 = make_float4(fmaf(w.x, u1, a1.x), fmaf(w.y, u1, a1.y),
                             fmaf(w.z, u1, a1.z), fmaf(w.w, u1, a1.w));
        }
        int vc = ct & (VCOP - 1);
        float* d0 = &g_va[e][vc][0][tid * 4];
        float* d1 = &g_va[e][vc][1][tid * 4];
        atomicAdd(d0 + 0, a0.x); atomicAdd(d0 + 1, a0.y);
        atomicAdd(d0 + 2, a0.z); atomicAdd(d0 + 3, a0.w);
        atomicAdd(d1 + 0, a1.x); atomicAdd(d1 + 1, a1.y);
        atomicAdd(d1 + 2, a1.z); atomicAdd(d1 + 3, a1.w);
    }
}

// ---- K3: scores[b,n] = 0.125 * X[b,n,:] . v[b]. X is L2-hot from K1. ----
__global__ void __launch_bounds__(T) k3_scores(const float4* __restrict__ X4,
                                               float* __restrict__ out) {
    __shared__ float4 sh[CG];
    __shared__ int e_sh;
    const int ct = blockIdx.x, tid = threadIdx.x;
    const int wid = tid >> 5, lane = tid & 31;
    if (tid == 0) {
        unsigned old = atomicAdd(&g_cnt[2], 1u);
        e_sh = (int)((old / G3) & 1u);
    }
    __syncthreads();
    const int e = e_sh;
    const int b = ct & 1, chunk = ct >> 1;

    if (tid < CG) {
        float4 acc = make_float4(0.f, 0.f, 0.f, 0.f);
#pragma unroll
        for (int c = 0; c < VCOP; ++c)
            acc = f4add(acc, *(const float4*)&g_va[e][c][b][tid * 4]);
        sh[tid] = acc;
    }
    __syncthreads();

    int nbase = chunk * 16 + wid * 2;
    float a[2];
#pragma unroll
    for (int r = 0; r < 2; ++r) {
        const float4* x = X4 + ((size_t)b * N + nbase + r) * CG;
        float acc = 0.f;
#pragma unroll
        for (int k = 0; k < 6; ++k) {
            int c4 = lane + k * 32;
            float4 xv = x[c4];
            float4 vv = sh[c4];
            acc += xv.x * vv.x + xv.y * vv.y + xv.z * vv.z + xv.w * vv.w;
        }
        a[r] = acc;
    }
#pragma unroll
    for (int o = 16; o > 0; o >>= 1) {
#pragma unroll
        for (int r = 0; r < 2; ++r)
            a[r] += __shfl_down_sync(0xFFFFFFFFu, a[r], o);
    }
    if (lane == 0) {
#pragma unroll
        for (int r = 0; r < 2; ++r)
            out[b * N + nbase + r] = 0.125f * a[r];
    }
}

extern "C" void kernel_launch(void* const* d_in, const int* in_sizes, int n_in,
                              void* d_out, int out_size) {
    const float4* X4 = (const float4*)d_in[0];  // [2, 2048, 768] f32
    const float4* W4 = (const float4*)d_in[1];  // [1536, 768] f32
    float* out = (float*)d_out;                 // [2, 2048] f32
    (void)in_sizes; (void)n_in; (void)out_size;

    k1_colsum<<<G1, T1>>>(X4, W4);
    k2_rank1<<<G2, T>>>(W4);
    k3_scores<<<G3, T>>>(X4, out);
}